// round 4
// baseline (speedup 1.0000x reference)
#include <cuda_runtime.h>
#include <math.h>

// ---------------- problem constants ----------------
#define B_ 16
#define T_ 2048
#define H_ 1024
#define H4 (H_ / 4)          // 256 float4 per row
#define BT 32                // timesteps per alphas block
#define NCHUNK (T_ / BT)     // 64 chunks per batch
#define NS B_                // scan blocks (bid 0..15)
#define NA (NCHUNK * B_)     // alphas blocks (bid 16..1039)

// ---------------- device scratch (no allocations allowed) ----------------
__device__ float g_alphas[B_ * T_];
__device__ float g_dist[B_ * T_];
__device__ int   g_fire_t[B_ * T_];
__device__ int   g_aflag[NA];    // alphas chunk-done flags
__device__ int   g_nfprog[B_];   // fires published so far per batch
__device__ int   g_sdone[B_];    // scan fully done per batch
__device__ float g_dummy_len[B_];
__device__ float g_dummy_fires[B_ * T_];

// ---------------- init: reset pipeline flags each call ---------------------
__global__ void init_kernel() {
    int i = blockIdx.x * blockDim.x + threadIdx.x;
    if (i < NA) g_aflag[i] = 0;
    if (i < B_) { g_nfprog[i] = 0; g_sdone[i] = 0; }
}

// ---------------- alphas math helper ----------------
__device__ __forceinline__ float part1(float xm, float x0, float xp,
                                       float w0, float w1, float w2,
                                       float cb, float lw) {
    float v = fmaf(w0, xm, fmaf(w1, x0, fmaf(w2, xp, cb)));
    v += x0;                 // residual
    v = fmaxf(v, 0.0f);      // relu
    return lw * v;
}

// ---------------- fused pipelined kernel -----------------------------------
// bid  0..15          : scan (batch = bid), consumes alphas chunks as they land
// bid 16..1039        : alphas chunk (chunk-major: ab = chunk*16 + b)
// bid 1040..1040+16L  : gather row (r-major: idx = r*16 + b)
__global__ __launch_bounds__(256) void fused_kernel(
    const float* __restrict__ hidden, const float* __restrict__ conv_w,
    const float* __restrict__ conv_b, const float* __restrict__ lin_w,
    const float* __restrict__ lin_b,
    float* __restrict__ out_cif, float* __restrict__ out_len,
    float* __restrict__ out_fires, int L)
{
    __shared__ float s_f[T_];            // scan: fires staging
    __shared__ float s_d[T_];            // scan: dist staging
    __shared__ int   s_ft[T_];           // scan: fire_t staging
    __shared__ int   s_cnf[NCHUNK + 1];  // scan: cumulative fires per chunk
    __shared__ float s_wpart[4][8];      // alphas: warp partials
    __shared__ int   s_np;               // gather: published fire count

    const int bid = blockIdx.x;
    const int tid = threadIdx.x;

    if (bid < NS) {
        // ================= SCAN (exact fp32 replication) =================
        const int b = bid;
        const int bT = b * T_;
        if (tid == 0) s_cnf[0] = 0;

        float integ = 0.0f;
        int nf = 0;
        for (int c = 0; c < NCHUNK; ++c) {
            if (tid == 0) {
                // wait for alphas chunk c of this batch
                while (((volatile int*)g_aflag)[c * B_ + b] == 0) __nanosleep(64);
                __threadfence();
                const float4* ap = (const float4*)(g_alphas + bT + c * BT);
                float4 av[BT / 4];
#pragma unroll
                for (int i = 0; i < BT / 4; ++i) av[i] = __ldcg(ap + i);
                const float* a = (const float*)av;
                const int tbase = c * BT;
#pragma unroll
                for (int j = 0; j < BT; ++j) {
                    const float aj = a[j];
                    const float t1 = integ + aj;       // fires (pre-subtract)
                    const float dist = 1.0f - integ;   // distribution completion
                    const float t2 = t1 - 1.0f;        // exact on [1,2) (Sterbenz)
                    const bool fire = (t1 >= 1.0f);
                    s_f[tbase + j] = t1;
                    s_d[tbase + j] = dist;
                    s_ft[nf] = tbase + j;              // kept iff fire
                    nf += fire ? 1 : 0;
                    integ = fire ? t2 : t1;
                }
                s_cnf[c + 1] = nf;
            }
            __syncthreads();
            const int lo = s_cnf[c], hi = s_cnf[c + 1];
            const int tbase = c * BT;
            if (tid < BT)
                out_fires[bT + tbase + tid] = s_f[tbase + tid];
            else if (tid < 2 * BT)
                g_dist[bT + tbase + (tid - BT)] = s_d[tbase + (tid - BT)];
            else if (tid - 2 * BT < hi - lo)
                g_fire_t[bT + lo + (tid - 2 * BT)] = s_ft[lo + (tid - 2 * BT)];
            __threadfence();
            __syncthreads();
            if (tid == 0) atomicExch(&g_nfprog[b], hi);
        }
        if (tid == 0) {
            out_len[b] = integ + (float)nf;   // == fp-sum of alphas (~1e-7)
            __threadfence();
            atomicExch(&g_sdone[b], 1);
        }
    } else if (bid < NS + NA) {
        // ================= ALPHAS =================
        const int ab = bid - NS;
        const int chunk = ab >> 4;
        const int b = ab & 15;
        const int tstart = chunk * BT;
        const int lane = tid & 31;
        const int warp = tid >> 5;

        const int h0 = tid * 4;
        float w0[4], w1[4], w2[4], cb[4], lw[4];
#pragma unroll
        for (int j = 0; j < 4; j++) {
            w0[j] = conv_w[(h0 + j) * 3 + 0];
            w1[j] = conv_w[(h0 + j) * 3 + 1];
            w2[j] = conv_w[(h0 + j) * 3 + 2];
            cb[j] = conv_b[h0 + j];
            lw[j] = lin_w[h0 + j];
        }
        const float lb = lin_b[0];

        const float4* Hb = (const float4*)hidden + (size_t)b * T_ * H4;
        const float4 z4 = make_float4(0.f, 0.f, 0.f, 0.f);

        float4 xm = (tstart > 0) ? __ldg(&Hb[(size_t)(tstart - 1) * H4 + tid]) : z4;
        float4 x0 = __ldg(&Hb[(size_t)tstart * H4 + tid]);

        for (int c = 0; c < BT / 4; ++c) {
            const int t0 = tstart + c * 4;
            float4 xA = __ldg(&Hb[(size_t)(t0 + 1) * H4 + tid]);
            float4 xB = __ldg(&Hb[(size_t)(t0 + 2) * H4 + tid]);
            float4 xC = __ldg(&Hb[(size_t)(t0 + 3) * H4 + tid]);
            float4 xD = (t0 + 4 < T_) ? __ldg(&Hb[(size_t)(t0 + 4) * H4 + tid]) : z4;

            float s[4];
            {
                const float4* P[6] = { &xm, &x0, &xA, &xB, &xC, &xD };
#pragma unroll
                for (int i = 0; i < 4; i++) {
                    const float4 a = *P[i], m = *P[i + 1], p = *P[i + 2];
                    float acc;
                    acc  = part1(a.x, m.x, p.x, w0[0], w1[0], w2[0], cb[0], lw[0]);
                    acc += part1(a.y, m.y, p.y, w0[1], w1[1], w2[1], cb[1], lw[1]);
                    acc += part1(a.z, m.z, p.z, w0[2], w1[2], w2[2], cb[2], lw[2]);
                    acc += part1(a.w, m.w, p.w, w0[3], w1[3], w2[3], cb[3], lw[3]);
                    s[i] = acc;
                }
            }
#pragma unroll
            for (int i = 0; i < 4; i++) {
#pragma unroll
                for (int off = 16; off; off >>= 1)
                    s[i] += __shfl_xor_sync(0xffffffffu, s[i], off);
            }
            if (lane == 0) {
#pragma unroll
                for (int i = 0; i < 4; i++) s_wpart[i][warp] = s[i];
            }
            __syncthreads();
            if (tid < 4) {
                float tot = lb;
#pragma unroll
                for (int w = 0; w < 8; w++) tot += s_wpart[tid][w];
                g_alphas[b * T_ + t0 + tid] = 1.0f / (1.0f + expf(-tot));
            }
            __syncthreads();
            xm = xC;
            x0 = xD;
        }
        __threadfence();
        __syncthreads();
        if (tid == 0) atomicExch(&g_aflag[ab], 1);   // publish chunk
    } else {
        // ================= GATHER =================
        const int idx = bid - NS - NA;
        const int r = idx >> 4;
        const int b = idx & 15;
        if (r >= L) return;

        if (tid == 0) {
            int np;
            while (true) {
                np = ((volatile int*)g_nfprog)[b];
                if (np > r) break;
                if (((volatile int*)g_sdone)[b] != 0) {
                    np = ((volatile int*)g_nfprog)[b];
                    break;
                }
                __nanosleep(128);
            }
            s_np = np;
        }
        __syncthreads();
        __threadfence();
        const int np = s_np;

        float4* orow = (float4*)out_cif + ((size_t)b * L + r) * H4;
        if (r >= np) {                       // padding row
            orow[tid] = make_float4(0.f, 0.f, 0.f, 0.f);
            return;
        }
        const int bT = b * T_;
        const int t1 = __ldcg(&g_fire_t[bT + r]);
        const float4* Hb = (const float4*)hidden + (size_t)b * T_ * H4;

        float4 acc = make_float4(0.f, 0.f, 0.f, 0.f);
        int ts = 0;
        if (r > 0) {
            const int t0 = __ldcg(&g_fire_t[bT + r - 1]);
            const float a0 = __ldcg(&g_alphas[bT + t0]);
            const float d0 = __ldcg(&g_dist[bT + t0]);
            const float rem = a0 - d0;       // bit-identical to scan's rem
            const float4 h = __ldg(&Hb[(size_t)t0 * H4 + tid]);
            acc.x = rem * h.x; acc.y = rem * h.y;
            acc.z = rem * h.z; acc.w = rem * h.w;
            ts = t0 + 1;
        }
        for (int t = ts; t < t1; ++t) {
            const float a = __ldcg(&g_alphas[bT + t]);
            const float4 h = __ldg(&Hb[(size_t)t * H4 + tid]);
            acc.x = fmaf(a, h.x, acc.x); acc.y = fmaf(a, h.y, acc.y);
            acc.z = fmaf(a, h.z, acc.z); acc.w = fmaf(a, h.w, acc.w);
        }
        {
            const float d1 = __ldcg(&g_dist[bT + t1]);
            const float4 h = __ldg(&Hb[(size_t)t1 * H4 + tid]);
            acc.x = fmaf(d1, h.x, acc.x); acc.y = fmaf(d1, h.y, acc.y);
            acc.z = fmaf(d1, h.z, acc.z); acc.w = fmaf(d1, h.w, acc.w);
        }
        orow[tid] = acc;
    }
}

// ---------------- launch ---------------------------------------------------
extern "C" void kernel_launch(void* const* d_in, const int* in_sizes, int n_in,
                              void* d_out, int out_size)
{
    const float* hidden = (const float*)d_in[0];
    const float* conv_w = (const float*)d_in[1];
    const float* conv_b = (const float*)d_in[2];
    const float* lin_w  = (const float*)d_in[3];
    const float* lin_b  = (const float*)d_in[4];

    float* out = (float*)d_out;

    // Output layout: tuple (cif_output[B,L,H], cif_length[B], fires[B,T])
    const long long fixed = (long long)B_ + (long long)B_ * T_;
    long long rem = (long long)out_size - fixed;
    int L;
    float* out_cif;
    float* out_len;
    float* out_fires;
    if (rem > 0 && rem % ((long long)B_ * H_) == 0) {
        L = (int)(rem / ((long long)B_ * H_));
        out_cif   = out;
        out_len   = out + (size_t)B_ * L * H_;
        out_fires = out_len + B_;
    } else {
        L = (int)((long long)out_size / ((long long)B_ * H_));
        out_cif = out;
        cudaGetSymbolAddress((void**)&out_len, g_dummy_len);
        cudaGetSymbolAddress((void**)&out_fires, g_dummy_fires);
    }

    init_kernel<<<4, 256>>>();
    const int grid = NS + NA + B_ * L;
    fused_kernel<<<grid, 256>>>(hidden, conv_w, conv_b, lin_w, lin_b,
                                out_cif, out_len, out_fires, L);
}

// round 5
// speedup vs baseline: 2.1594x; 2.1594x over previous
#include <cuda_runtime.h>
#include <math.h>

// ---------------- problem constants ----------------
#define B_ 16
#define T_ 2048
#define H_ 1024
#define H4 (H_ / 4)      // 256 float4 per row
#define BT 32            // timesteps per block in alphas kernel (grid = 1024)
#define RPB 8            // output rows per gather block

// ---------------- device scratch (no allocations allowed) ----------------
__device__ float g_alphas[B_ * T_];
__device__ float g_dist[B_ * T_];
__device__ int   g_fire_t[B_ * T_];
__device__ int   g_nf[B_];
__device__ float g_dummy_len[B_];
__device__ float g_dummy_fires[B_ * T_];

// ---------------- kernel A: alphas = sigmoid(lin(relu(dwconv3(x)+x))) ------
// grid (T/BT, B), 256 threads, each owns 4 h (one float4). All 32 timestep
// warp-partials staged in smem; ONE barrier per block (was 16).
__device__ __forceinline__ float part1(float xm, float x0, float xp,
                                       float w0, float w1, float w2,
                                       float cb, float lw) {
    float v = fmaf(w0, xm, fmaf(w1, x0, fmaf(w2, xp, cb)));
    v += x0;                 // residual
    v = fmaxf(v, 0.0f);      // relu
    return lw * v;
}

__global__ __launch_bounds__(256) void alphas_kernel(
    const float* __restrict__ hidden, const float* __restrict__ conv_w,
    const float* __restrict__ conv_b, const float* __restrict__ lin_w,
    const float* __restrict__ lin_b)
{
    const int b = blockIdx.y;
    const int tstart = blockIdx.x * BT;
    const int tid = threadIdx.x;
    const int lane = tid & 31;
    const int warp = tid >> 5;

    __shared__ float wpart[BT][9];   // [timestep][warp], padded: conflict-free

    const int h0 = tid * 4;
    float w0[4], w1[4], w2[4], cb[4], lw[4];
#pragma unroll
    for (int j = 0; j < 4; j++) {
        w0[j] = conv_w[(h0 + j) * 3 + 0];
        w1[j] = conv_w[(h0 + j) * 3 + 1];
        w2[j] = conv_w[(h0 + j) * 3 + 2];
        cb[j] = conv_b[h0 + j];
        lw[j] = lin_w[h0 + j];
    }

    const float4* Hb = (const float4*)hidden + (size_t)b * T_ * H4;
    const float4 z4 = make_float4(0.f, 0.f, 0.f, 0.f);

    float4 xm = (tstart > 0) ? __ldg(&Hb[(size_t)(tstart - 1) * H4 + tid]) : z4;
    float4 x0 = __ldg(&Hb[(size_t)tstart * H4 + tid]);

#pragma unroll 2
    for (int c = 0; c < BT / 4; ++c) {
        const int t0 = tstart + c * 4;
        // prefetch 4 future rows together (MLP=4 per thread)
        float4 xA = __ldg(&Hb[(size_t)(t0 + 1) * H4 + tid]);
        float4 xB = __ldg(&Hb[(size_t)(t0 + 2) * H4 + tid]);
        float4 xC = __ldg(&Hb[(size_t)(t0 + 3) * H4 + tid]);
        float4 xD = (t0 + 4 < T_) ? __ldg(&Hb[(size_t)(t0 + 4) * H4 + tid]) : z4;

        float s[4];
        {
            const float4* P[6] = { &xm, &x0, &xA, &xB, &xC, &xD };
#pragma unroll
            for (int i = 0; i < 4; i++) {
                const float4 a = *P[i], m = *P[i + 1], p = *P[i + 2];
                float acc;
                acc  = part1(a.x, m.x, p.x, w0[0], w1[0], w2[0], cb[0], lw[0]);
                acc += part1(a.y, m.y, p.y, w0[1], w1[1], w2[1], cb[1], lw[1]);
                acc += part1(a.z, m.z, p.z, w0[2], w1[2], w2[2], cb[2], lw[2]);
                acc += part1(a.w, m.w, p.w, w0[3], w1[3], w2[3], cb[3], lw[3]);
                s[i] = acc;
            }
        }
        // 4 independent warp reductions (ILP hides shfl latency)
#pragma unroll
        for (int i = 0; i < 4; i++) {
#pragma unroll
            for (int off = 16; off; off >>= 1)
                s[i] += __shfl_xor_sync(0xffffffffu, s[i], off);
        }
        if (lane == 0) {
#pragma unroll
            for (int i = 0; i < 4; i++) wpart[c * 4 + i][warp] = s[i];
        }
        xm = xC;
        x0 = xD;
    }
    __syncthreads();          // the ONLY barrier
    if (tid < BT) {
        float tot = lin_b[0];
#pragma unroll
        for (int w = 0; w < 8; w++) tot += wpart[tid][w];
        g_alphas[b * T_ + tstart + tid] = 1.0f / (1.0f + expf(-tot));
    }
}

// ---------------- kernel S: exact sequential integrate-and-fire scan -------
// One block per batch; thread 0 runs a branchless 12-cycle dependent chain.
// dist/fire_t stored unconditionally (non-fire fire_t slots overwritten).
__global__ __launch_bounds__(64) void scan_kernel(float* __restrict__ out_fires,
                                                  float* __restrict__ out_len)
{
    const int b = blockIdx.x;
    __shared__ float a_s[T_];
    __shared__ float fires_s[T_];
    __shared__ float dist_s[T_];

    const float* ab = g_alphas + b * T_;
    for (int i = threadIdx.x; i < T_; i += blockDim.x) a_s[i] = ab[i];
    __syncthreads();

    if (threadIdx.x == 0) {
        float integ = 0.0f;
        int nf = 0;
        const int base = b * T_;
        for (int t = 0; t < T_; t += 8) {
            float av[8];
#pragma unroll
            for (int j = 0; j < 8; j++) av[j] = a_s[t + j];
#pragma unroll
            for (int j = 0; j < 8; j++) {
                const float a = av[j];
                const float t1 = integ + a;        // fires value (pre-subtract)
                const float dist = 1.0f - integ;   // distribution completion
                const float t2 = t1 - 1.0f;        // exact on [1,2) (Sterbenz)
                const bool fire = (t1 >= 1.0f);
                fires_s[t + j] = t1;
                dist_s[t + j]  = dist;
                g_fire_t[base + nf] = t + j;       // unconditional; kept iff fire
                nf += fire ? 1 : 0;
                integ = fire ? t2 : t1;
            }
        }
        g_nf[b] = nf;
        out_len[b] = integ + (float)nf;            // == fp-sum of alphas
    }
    __syncthreads();

    float* fires = out_fires + b * T_;
    const int base = b * T_;
    for (int i = threadIdx.x; i < T_; i += blockDim.x) {
        fires[i]         = fires_s[i];
        g_dist[base + i] = dist_s[i];
    }
}

// ---------------- kernel C: streaming multi-row segment gather -------------
// grid (ceil(L/RPB), B), 256 threads x float4. Each block walks time forward
// once across RPB consecutive fire segments: every hidden row read exactly
// once, boundary rows reused in registers. Accumulation order == reference.
__global__ __launch_bounds__(256) void gather_kernel(
    const float* __restrict__ hidden, float* __restrict__ out, int L)
{
    const int b = blockIdx.y;
    const int r0 = blockIdx.x * RPB;
    const int tid = threadIdx.x;

    const int nf = g_nf[b];
    const int bT = b * T_;
    const int rlim = min(L, r0 + RPB);
    const int rend = min(nf, rlim);
    const float4* Hb = (const float4*)hidden + (size_t)b * T_ * H4;
    float4* Ob = (float4*)out + (size_t)b * L * H4;

    if (r0 < rend) {
        float4 acc = make_float4(0.f, 0.f, 0.f, 0.f);
        int ts = 0;
        if (r0 > 0) {
            const int t0 = g_fire_t[bT + r0 - 1];
            const float rem = g_alphas[bT + t0] - g_dist[bT + t0]; // == scan rem
            const float4 h = __ldg(&Hb[(size_t)t0 * H4 + tid]);
            acc.x = rem * h.x; acc.y = rem * h.y;
            acc.z = rem * h.z; acc.w = rem * h.w;
            ts = t0 + 1;
        }
        for (int r = r0; r < rend; ++r) {
            const int t1 = g_fire_t[bT + r];
#pragma unroll 2
            for (int t = ts; t < t1; ++t) {
                const float a = g_alphas[bT + t];       // uniform -> broadcast
                const float4 h = __ldg(&Hb[(size_t)t * H4 + tid]);
                acc.x = fmaf(a, h.x, acc.x); acc.y = fmaf(a, h.y, acc.y);
                acc.z = fmaf(a, h.z, acc.z); acc.w = fmaf(a, h.w, acc.w);
            }
            const float d1 = g_dist[bT + t1];
            const float a1 = g_alphas[bT + t1];
            const float4 h1 = __ldg(&Hb[(size_t)t1 * H4 + tid]);
            float4 o;
            o.x = fmaf(d1, h1.x, acc.x); o.y = fmaf(d1, h1.y, acc.y);
            o.z = fmaf(d1, h1.z, acc.z); o.w = fmaf(d1, h1.w, acc.w);
            Ob[(size_t)r * H4 + tid] = o;
            const float rem = a1 - d1;                  // opens next segment
            acc.x = rem * h1.x; acc.y = rem * h1.y;
            acc.z = rem * h1.z; acc.w = rem * h1.w;
            ts = t1 + 1;
        }
    }
    // zero-fill padding rows (r >= nf)
    const float4 z4 = make_float4(0.f, 0.f, 0.f, 0.f);
    for (int r = max(r0, rend); r < rlim; ++r)
        Ob[(size_t)r * H4 + tid] = z4;
}

// ---------------- launch ---------------------------------------------------
extern "C" void kernel_launch(void* const* d_in, const int* in_sizes, int n_in,
                              void* d_out, int out_size)
{
    const float* hidden = (const float*)d_in[0];
    const float* conv_w = (const float*)d_in[1];
    const float* conv_b = (const float*)d_in[2];
    const float* lin_w  = (const float*)d_in[3];
    const float* lin_b  = (const float*)d_in[4];

    float* out = (float*)d_out;

    // Output layout: tuple (cif_output[B,L,H], cif_length[B], fires[B,T])
    const long long fixed = (long long)B_ + (long long)B_ * T_;
    long long rem = (long long)out_size - fixed;
    int L;
    float* out_cif;
    float* out_len;
    float* out_fires;
    if (rem > 0 && rem % ((long long)B_ * H_) == 0) {
        L = (int)(rem / ((long long)B_ * H_));
        out_cif   = out;
        out_len   = out + (size_t)B_ * L * H_;
        out_fires = out_len + B_;
    } else {
        L = (int)((long long)out_size / ((long long)B_ * H_));
        out_cif = out;
        cudaGetSymbolAddress((void**)&out_len, g_dummy_len);
        cudaGetSymbolAddress((void**)&out_fires, g_dummy_fires);
    }

    alphas_kernel<<<dim3(T_ / BT, B_), 256>>>(hidden, conv_w, conv_b,
                                              lin_w, lin_b);
    scan_kernel<<<B_, 64>>>(out_fires, out_len);
    if (L > 0)
        gather_kernel<<<dim3((L + RPB - 1) / RPB, B_), 256>>>(hidden, out_cif, L);
}

// round 6
// speedup vs baseline: 2.4025x; 1.1126x over previous
#include <cuda_runtime.h>
#include <math.h>

// ---------------- problem constants ----------------
#define B_ 16
#define T_ 2048
#define H_ 1024
#define H4 (H_ / 4)      // 256 float4 per row
#define BT 32            // timesteps per block in alphas kernel (grid = 1024)
#define RPB 8            // output rows per gather block

// ---------------- device scratch (no allocations allowed) ----------------
__device__ float g_alphas[B_ * T_];
__device__ float g_dist[B_ * T_];
__device__ float g_rem[B_ * T_];
__device__ int   g_fire_t[B_ * T_];
__device__ int   g_nf[B_];
__device__ float g_dummy_len[B_];
__device__ float g_dummy_fires[B_ * T_];

// ---------------- kernel A: alphas = sigmoid(lin(relu(dwconv3(x)+x))) ------
// (R3 body verbatim — measured 33.0us @ 52.9% DRAM)
__device__ __forceinline__ float part1(float xm, float x0, float xp,
                                       float w0, float w1, float w2,
                                       float cb, float lw) {
    float v = fmaf(w0, xm, fmaf(w1, x0, fmaf(w2, xp, cb)));
    v += x0;                 // residual
    v = fmaxf(v, 0.0f);      // relu
    return lw * v;
}

__global__ __launch_bounds__(256) void alphas_kernel(
    const float* __restrict__ hidden, const float* __restrict__ conv_w,
    const float* __restrict__ conv_b, const float* __restrict__ lin_w,
    const float* __restrict__ lin_b)
{
    const int b = blockIdx.y;
    const int tstart = blockIdx.x * BT;
    const int tid = threadIdx.x;
    const int lane = tid & 31;
    const int warp = tid >> 5;

    __shared__ float wpart[4][8];   // [t within group][warp]

    const int h0 = tid * 4;
    float w0[4], w1[4], w2[4], cb[4], lw[4];
#pragma unroll
    for (int j = 0; j < 4; j++) {
        w0[j] = conv_w[(h0 + j) * 3 + 0];
        w1[j] = conv_w[(h0 + j) * 3 + 1];
        w2[j] = conv_w[(h0 + j) * 3 + 2];
        cb[j] = conv_b[h0 + j];
        lw[j] = lin_w[h0 + j];
    }
    const float lb = lin_b[0];

    const float4* Hb = (const float4*)hidden + (size_t)b * T_ * H4;
    const float4 z4 = make_float4(0.f, 0.f, 0.f, 0.f);

    float4 xm = (tstart > 0) ? Hb[(size_t)(tstart - 1) * H4 + tid] : z4;
    float4 x0 = Hb[(size_t)tstart * H4 + tid];

    for (int c = 0; c < BT / 4; ++c) {
        const int t0 = tstart + c * 4;
        // prefetch 4 future rows together (MLP=4 per thread)
        float4 xA = Hb[(size_t)(t0 + 1) * H4 + tid];
        float4 xB = Hb[(size_t)(t0 + 2) * H4 + tid];
        float4 xC = Hb[(size_t)(t0 + 3) * H4 + tid];
        float4 xD = (t0 + 4 < T_) ? Hb[(size_t)(t0 + 4) * H4 + tid] : z4;

        float s[4];
        {
            const float4* P[6] = { &xm, &x0, &xA, &xB, &xC, &xD };
#pragma unroll
            for (int i = 0; i < 4; i++) {
                const float4 a = *P[i], m = *P[i + 1], p = *P[i + 2];
                float acc;
                acc  = part1(a.x, m.x, p.x, w0[0], w1[0], w2[0], cb[0], lw[0]);
                acc += part1(a.y, m.y, p.y, w0[1], w1[1], w2[1], cb[1], lw[1]);
                acc += part1(a.z, m.z, p.z, w0[2], w1[2], w2[2], cb[2], lw[2]);
                acc += part1(a.w, m.w, p.w, w0[3], w1[3], w2[3], cb[3], lw[3]);
                s[i] = acc;
            }
        }
#pragma unroll
        for (int i = 0; i < 4; i++) {
#pragma unroll
            for (int off = 16; off; off >>= 1)
                s[i] += __shfl_xor_sync(0xffffffffu, s[i], off);
        }
        if (lane == 0) {
#pragma unroll
            for (int i = 0; i < 4; i++) wpart[i][warp] = s[i];
        }
        __syncthreads();
        if (tid < 4) {
            float tot = lb;
#pragma unroll
            for (int w = 0; w < 8; w++) tot += wpart[tid][w];
            g_alphas[b * T_ + t0 + tid] = 1.0f / (1.0f + expf(-tot));
        }
        __syncthreads();
        xm = xC;
        x0 = xD;
    }
}

// ---------------- kernel S: exact sequential integrate-and-fire scan -------
// One block per batch; thread 0 runs a branchless 12-cycle dependent chain.
// All outputs (fires, dist, rem, fire_t) staged in smem (STS issue-only) and
// flushed by 128 threads after the loop.
__global__ __launch_bounds__(128) void scan_kernel(float* __restrict__ out_fires,
                                                   float* __restrict__ out_len)
{
    const int b = blockIdx.x;
    __shared__ float a_s[T_];
    __shared__ float fires_s[T_];
    __shared__ float dist_s[T_];
    __shared__ float rem_s[T_];
    __shared__ int   ft_s[T_];
    __shared__ int   s_nf;

    const float* ab = g_alphas + b * T_;
    for (int i = threadIdx.x; i < T_; i += blockDim.x) a_s[i] = ab[i];
    __syncthreads();

    if (threadIdx.x == 0) {
        float integ = 0.0f;
        int nf = 0;
        for (int t = 0; t < T_; t += 8) {
            float av[8];
#pragma unroll
            for (int j = 0; j < 8; j++) av[j] = a_s[t + j];
#pragma unroll
            for (int j = 0; j < 8; j++) {
                const float a = av[j];
                const float t1 = integ + a;        // fires value (pre-subtract)
                const float dist = 1.0f - integ;   // distribution completion
                const float t2 = t1 - 1.0f;        // exact on [1,2) (Sterbenz)
                const bool fire = (t1 >= 1.0f);
                fires_s[t + j] = t1;
                dist_s[t + j]  = dist;
                rem_s[t + j]   = a - dist;
                ft_s[nf] = t + j;                  // unconditional; kept iff fire
                nf += fire ? 1 : 0;
                integ = fire ? t2 : t1;
            }
        }
        s_nf = nf;
        g_nf[b] = nf;
        out_len[b] = integ + (float)nf;            // == fp-sum of alphas
    }
    __syncthreads();

    const int nf = s_nf;
    float* fires = out_fires + b * T_;
    const int base = b * T_;
    for (int i = threadIdx.x; i < T_; i += blockDim.x) {
        fires[i]         = fires_s[i];
        g_dist[base + i] = dist_s[i];
        g_rem[base + i]  = rem_s[i];
    }
    for (int i = threadIdx.x; i < nf; i += blockDim.x)
        g_fire_t[base + i] = ft_s[i];
}

// ---------------- kernel C: tile-batched streaming gather ------------------
// grid (ceil(L/RPB), B), 256 threads x float4. Block preloads its fire
// boundaries (+dist/rem), then walks its contiguous t-range in tiles of 4
// FRONT-BATCHED LDG.128 (MLP_p1=4). Emit logic is warp-uniform per step.
// Accumulation order == reference (time-ascending within each row).
__global__ __launch_bounds__(256) void gather_kernel(
    const float* __restrict__ hidden, float* __restrict__ out, int L)
{
    const int b = blockIdx.y;
    const int r0 = blockIdx.x * RPB;
    const int tid = threadIdx.x;

    __shared__ int   s_ft[RPB];
    __shared__ float s_dist[RPB];
    __shared__ float s_rem[RPB];
    __shared__ float s_remprev;
    __shared__ int   s_tprev;

    const int nf = g_nf[b];
    const int bT = b * T_;
    const int rlim = min(L, r0 + RPB);
    const int rend = min(nf, rlim);
    const int nr = rend - r0;               // real rows in this block

    if (tid < RPB && tid < nr) {
        const int ft = g_fire_t[bT + r0 + tid];
        s_ft[tid]   = ft;
        s_dist[tid] = g_dist[bT + ft];
        s_rem[tid]  = g_rem[bT + ft];
    }
    if (tid == 0) {
        if (r0 > 0 && nr > 0) {
            const int tp = g_fire_t[bT + r0 - 1];
            s_tprev = tp;
            s_remprev = g_rem[bT + tp];
        } else {
            s_tprev = -1;
            s_remprev = 0.0f;
        }
    }
    __syncthreads();

    const float4* Hb = (const float4*)hidden + (size_t)b * T_ * H4;
    float4* Ob = (float4*)out + (size_t)b * L * H4;

    if (nr > 0) {
        float4 acc = make_float4(0.f, 0.f, 0.f, 0.f);
        int ts = 0;
        if (s_tprev >= 0) {
            const float rp = s_remprev;
            const float4 h = __ldg(&Hb[(size_t)s_tprev * H4 + tid]);
            acc.x = rp * h.x; acc.y = rp * h.y;
            acc.z = rp * h.z; acc.w = rp * h.w;
            ts = s_tprev + 1;
        }
        const int thi = s_ft[nr - 1];        // inclusive end
        int k = 0;
        int t1 = s_ft[0];
        const float* Ab = g_alphas + bT;

        for (int t = ts; t <= thi; t += 4) {
            // front-batched tile loads (addresses independent of acc)
            const int i0 = t, i1 = min(t + 1, thi), i2 = min(t + 2, thi),
                      i3 = min(t + 3, thi);
            const float4 h0 = __ldg(&Hb[(size_t)i0 * H4 + tid]);
            const float4 h1 = __ldg(&Hb[(size_t)i1 * H4 + tid]);
            const float4 h2 = __ldg(&Hb[(size_t)i2 * H4 + tid]);
            const float4 h3 = __ldg(&Hb[(size_t)i3 * H4 + tid]);
            const float a0 = __ldg(Ab + i0);
            const float a1 = __ldg(Ab + i1);
            const float a2 = __ldg(Ab + i2);
            const float a3 = __ldg(Ab + i3);
            const float4 hv[4] = { h0, h1, h2, h3 };
            const float  av[4] = { a0, a1, a2, a3 };
#pragma unroll
            for (int j = 0; j < 4; j++) {
                const int tt = t + j;
                if (tt > thi) break;
                const float4 h = hv[j];
                if (tt == t1) {              // fire: close row k
                    const float d = s_dist[k];
                    float4 o;
                    o.x = fmaf(d, h.x, acc.x); o.y = fmaf(d, h.y, acc.y);
                    o.z = fmaf(d, h.z, acc.z); o.w = fmaf(d, h.w, acc.w);
                    Ob[(size_t)(r0 + k) * H4 + tid] = o;
                    const float rm = s_rem[k];
                    acc.x = rm * h.x; acc.y = rm * h.y;
                    acc.z = rm * h.z; acc.w = rm * h.w;
                    ++k;
                    t1 = (k < nr) ? s_ft[k] : -1;
                } else {                     // interior: accumulate
                    const float a = av[j];
                    acc.x = fmaf(a, h.x, acc.x); acc.y = fmaf(a, h.y, acc.y);
                    acc.z = fmaf(a, h.z, acc.z); acc.w = fmaf(a, h.w, acc.w);
                }
            }
        }
    }
    // zero-fill padding rows (r >= nf)
    const float4 z4 = make_float4(0.f, 0.f, 0.f, 0.f);
    for (int r = r0 + max(nr, 0); r < rlim; ++r)
        Ob[(size_t)r * H4 + tid] = z4;
}

// ---------------- launch ---------------------------------------------------
extern "C" void kernel_launch(void* const* d_in, const int* in_sizes, int n_in,
                              void* d_out, int out_size)
{
    const float* hidden = (const float*)d_in[0];
    const float* conv_w = (const float*)d_in[1];
    const float* conv_b = (const float*)d_in[2];
    const float* lin_w  = (const float*)d_in[3];
    const float* lin_b  = (const float*)d_in[4];

    float* out = (float*)d_out;

    // Output layout: tuple (cif_output[B,L,H], cif_length[B], fires[B,T])
    const long long fixed = (long long)B_ + (long long)B_ * T_;
    long long rem = (long long)out_size - fixed;
    int L;
    float* out_cif;
    float* out_len;
    float* out_fires;
    if (rem > 0 && rem % ((long long)B_ * H_) == 0) {
        L = (int)(rem / ((long long)B_ * H_));
        out_cif   = out;
        out_len   = out + (size_t)B_ * L * H_;
        out_fires = out_len + B_;
    } else {
        L = (int)((long long)out_size / ((long long)B_ * H_));
        out_cif = out;
        cudaGetSymbolAddress((void**)&out_len, g_dummy_len);
        cudaGetSymbolAddress((void**)&out_fires, g_dummy_fires);
    }

    alphas_kernel<<<dim3(T_ / BT, B_), 256>>>(hidden, conv_w, conv_b,
                                              lin_w, lin_b);
    scan_kernel<<<B_, 128>>>(out_fires, out_len);
    if (L > 0)
        gather_kernel<<<dim3((L + RPB - 1) / RPB, B_), 256>>>(hidden, out_cif, L);
}